// round 3
// baseline (speedup 1.0000x reference)
#include <cuda_runtime.h>
#include <cuda_bf16.h>

// Problem: logits[r] = sum_d fc[r][d] * input[d],  r in [0,50), D = 2^20.
// Pure HBM-streaming matvec. fc (200 MB) read once; input (4 MB) L2-resident.
//
// Pass 1: grid (128 chunks, 50 rows); each block dot-products an 8192-float
//         chunk with fully vectorized float4 loads, reduces to one partial.
// Pass 2: 50 blocks of 128 threads reduce the 128 partials per row.
// Partials live in a __device__ global (overwritten every launch ->
// deterministic under graph replay, no memset, no atomics into d_out).

#define D_ELEMS   (1 << 20)
#define N_ROWS    50
#define TPB       256
#define V4_PER_T  8
#define CHUNK_F   (TPB * V4_PER_T * 4)      // 8192 floats per block
#define N_CHUNKS  (D_ELEMS / CHUNK_F)       // 128

__device__ float g_partials[N_ROWS * N_CHUNKS];

__global__ __launch_bounds__(TPB) void matvec_partial_kernel(
    const float4* __restrict__ inp,   // [D/4]
    const float4* __restrict__ fc)    // [N_ROWS * D/4]
{
    const int chunk = blockIdx.x;     // 0..127
    const int row   = blockIdx.y;     // 0..49
    const int t     = threadIdx.x;

    const float4* a = inp + (size_t)chunk * (CHUNK_F / 4);
    const float4* b = fc  + (size_t)row * (D_ELEMS / 4)
                          + (size_t)chunk * (CHUNK_F / 4);

    float sum = 0.0f;

    // Two half-batches of loads: MLP=8 per operand group keeps DRAM latency
    // covered while limiting cross-CTA L1tex queue depth (spread model).
#pragma unroll
    for (int h = 0; h < 2; h++) {
        float4 av[V4_PER_T / 2];
        float4 bv[V4_PER_T / 2];
#pragma unroll
        for (int i = 0; i < V4_PER_T / 2; i++) {
            const int idx = t + (h * (V4_PER_T / 2) + i) * TPB;
            av[i] = __ldg(&a[idx]);
            bv[i] = __ldg(&b[idx]);
        }
#pragma unroll
        for (int i = 0; i < V4_PER_T / 2; i++) {
            sum += av[i].x * bv[i].x;
            sum += av[i].y * bv[i].y;
            sum += av[i].z * bv[i].z;
            sum += av[i].w * bv[i].w;
        }
    }

    // Intra-warp reduce
#pragma unroll
    for (int off = 16; off > 0; off >>= 1)
        sum += __shfl_down_sync(0xFFFFFFFFu, sum, off);

    __shared__ float s_warp[TPB / 32];
    if ((t & 31) == 0) s_warp[t >> 5] = sum;
    __syncthreads();

    if (t < (TPB / 32)) {
        float v = s_warp[t];
#pragma unroll
        for (int off = (TPB / 64); off > 0; off >>= 1)
            v += __shfl_down_sync(0xFFu, v, off);
        if (t == 0)
            g_partials[row * N_CHUNKS + chunk] = v;
    }
}

__global__ __launch_bounds__(N_CHUNKS) void reduce_kernel(float* __restrict__ out)
{
    const int row = blockIdx.x;       // 0..49
    const int t   = threadIdx.x;      // 0..127

    float v = g_partials[row * N_CHUNKS + t];

#pragma unroll
    for (int off = 16; off > 0; off >>= 1)
        v += __shfl_down_sync(0xFFFFFFFFu, v, off);

    __shared__ float s_warp[N_CHUNKS / 32];   // 4
    if ((t & 31) == 0) s_warp[t >> 5] = v;
    __syncthreads();

    if (t == 0) {
        float r = s_warp[0] + s_warp[1] + s_warp[2] + s_warp[3];
        out[row] = r;
    }
}

extern "C" void kernel_launch(void* const* d_in, const int* in_sizes, int n_in,
                              void* d_out, int out_size)
{
    // Disambiguate operands by element count (robust to metadata ordering):
    // input has D elements, fc has N_ROWS*D elements.
    const float4* inp;
    const float4* fc;
    if (in_sizes[0] == D_ELEMS) {
        inp = (const float4*)d_in[0];
        fc  = (const float4*)d_in[1];
    } else {
        fc  = (const float4*)d_in[0];
        inp = (const float4*)d_in[1];
    }
    float* out = (float*)d_out;                   // [50]

    dim3 grid(N_CHUNKS, N_ROWS);
    matvec_partial_kernel<<<grid, TPB>>>(inp, fc);
    reduce_kernel<<<N_ROWS, N_CHUNKS>>>(out);
}